// round 1
// baseline (speedup 1.0000x reference)
#include <cuda_runtime.h>

#define NPTS 120000
#define INC  256
#define MIDC 64
#define OUTC 256
#define KNB  27
#define EPSV 1e-5f
#define PAD  68   // row stride (floats) for 64-wide smem tiles: kills bank conflicts, keeps 16B align

// ---------------- scratch (no allocations allowed -> __device__ globals) ----------------
__device__ float g_h1[(size_t)NPTS * MIDC];   // raw x@W1
__device__ float g_h2[(size_t)NPTS * MIDC];   // raw gather-gemm output
__device__ float g_h3[(size_t)NPTS * OUTC];   // raw h@W2
__device__ float g_sum1[MIDC], g_ssq1[MIDC], g_a1[MIDC], g_c1[MIDC];
__device__ float g_sum2[MIDC], g_ssq2[MIDC], g_a2[MIDC], g_c2[MIDC];
__device__ float g_sum3[OUTC], g_ssq3[OUTC], g_a3[OUTC], g_c3[OUTC];

// ---------------- zero the stats accumulators (graph-replay safe) ----------------
__global__ void k_zero() {
    int t = threadIdx.x;
    if (t < MIDC) { g_sum1[t] = 0.f; g_ssq1[t] = 0.f; g_sum2[t] = 0.f; g_ssq2[t] = 0.f; }
    g_sum3[t] = 0.f; g_ssq3[t] = 0.f;
}

// ---------------- GEMM1: g_h1 = x[N,256] @ W1[256,64] (raw, pre-BN) ----------------
__global__ __launch_bounds__(256) void k_gemm1(const float* __restrict__ x,
                                               const float* __restrict__ W1) {
    __shared__ float As[64 * PAD];
    __shared__ float Bs[64 * PAD];
    const int tid  = threadIdx.x;
    const int p0   = blockIdx.x * 64;
    const int row0 = (tid >> 4) << 2;
    const int col0 = (tid & 15) << 2;
    float acc[4][4] = {};

    for (int kc = 0; kc < 4; kc++) {
        __syncthreads();
#pragma unroll
        for (int i = 0; i < 4; i++) {
            int j4 = tid + i * 256;
            int r = j4 >> 4, c = (j4 & 15) << 2;
            float4 av = *(const float4*)(x + (size_t)(p0 + r) * INC + kc * 64 + c);
            *(float4*)&As[r * PAD + c] = av;
            float4 bv = *(const float4*)(W1 + (size_t)(kc * 64 + r) * MIDC + c);
            *(float4*)&Bs[r * PAD + c] = bv;
        }
        __syncthreads();
#pragma unroll 16
        for (int kk = 0; kk < 64; kk++) {
            float4 bv = *(float4*)&Bs[kk * PAD + col0];
            float a0 = As[(row0 + 0) * PAD + kk];
            float a1 = As[(row0 + 1) * PAD + kk];
            float a2 = As[(row0 + 2) * PAD + kk];
            float a3 = As[(row0 + 3) * PAD + kk];
            acc[0][0] = fmaf(a0, bv.x, acc[0][0]); acc[0][1] = fmaf(a0, bv.y, acc[0][1]);
            acc[0][2] = fmaf(a0, bv.z, acc[0][2]); acc[0][3] = fmaf(a0, bv.w, acc[0][3]);
            acc[1][0] = fmaf(a1, bv.x, acc[1][0]); acc[1][1] = fmaf(a1, bv.y, acc[1][1]);
            acc[1][2] = fmaf(a1, bv.z, acc[1][2]); acc[1][3] = fmaf(a1, bv.w, acc[1][3]);
            acc[2][0] = fmaf(a2, bv.x, acc[2][0]); acc[2][1] = fmaf(a2, bv.y, acc[2][1]);
            acc[2][2] = fmaf(a2, bv.z, acc[2][2]); acc[2][3] = fmaf(a2, bv.w, acc[2][3]);
            acc[3][0] = fmaf(a3, bv.x, acc[3][0]); acc[3][1] = fmaf(a3, bv.y, acc[3][1]);
            acc[3][2] = fmaf(a3, bv.z, acc[3][2]); acc[3][3] = fmaf(a3, bv.w, acc[3][3]);
        }
    }
#pragma unroll
    for (int i = 0; i < 4; i++)
        *(float4*)&g_h1[(size_t)(p0 + row0 + i) * MIDC + col0] =
            make_float4(acc[i][0], acc[i][1], acc[i][2], acc[i][3]);
}

// ---------------- column stats for a [N,64] tensor (which: 0 -> h1, 1 -> h2) ----------------
__global__ __launch_bounds__(256) void k_stats_mid(int which) {
    const float* src = (which == 0) ? g_h1 : g_h2;
    float* sum = (which == 0) ? g_sum1 : g_sum2;
    float* ssq = (which == 0) ? g_ssq1 : g_ssq2;
    int tid = threadIdx.x;
    int c = tid & 63, sub = tid >> 6;
    float s = 0.f, q = 0.f;
    for (int r = blockIdx.x * 4 + sub; r < NPTS; r += gridDim.x * 4) {
        float v = src[(size_t)r * MIDC + c];
        s += v; q += v * v;
    }
    __shared__ float ss[256], qq[256];
    ss[tid] = s; qq[tid] = q;
    __syncthreads();
    if (tid < 64) {
        s = ss[tid] + ss[tid + 64] + ss[tid + 128] + ss[tid + 192];
        q = qq[tid] + qq[tid + 64] + qq[tid + 128] + qq[tid + 192];
        atomicAdd(&sum[tid], s);
        atomicAdd(&ssq[tid], q);
    }
}

// ---------------- column stats for g_h3 [N,256] ----------------
__global__ __launch_bounds__(256) void k_stats_out() {
    int c = threadIdx.x;
    float s = 0.f, q = 0.f;
    for (int r = blockIdx.x; r < NPTS; r += gridDim.x) {
        float v = g_h3[(size_t)r * OUTC + c];
        s += v; q += v * v;
    }
    atomicAdd(&g_sum3[c], s);
    atomicAdd(&g_ssq3[c], q);
}

// ---------------- BN finalize: a = gamma*rsqrt(var+eps); c = beta - mean*a ----------------
__global__ void k_finalize(const float* __restrict__ g, const float* __restrict__ b, int which) {
    int i = threadIdx.x;
    int C = (which == 2) ? OUTC : MIDC;
    if (i >= C) return;
    const float* sum = (which == 0) ? g_sum1 : (which == 1) ? g_sum2 : g_sum3;
    const float* ssq = (which == 0) ? g_ssq1 : (which == 1) ? g_ssq2 : g_ssq3;
    float* a = (which == 0) ? g_a1 : (which == 1) ? g_a2 : g_a3;
    float* c = (which == 0) ? g_c1 : (which == 1) ? g_c2 : g_c3;
    float m = sum[i] * (1.f / NPTS);
    float v = ssq[i] * (1.f / NPTS) - m * m;
    float ai = g[i] * rsqrtf(v + EPSV);
    a[i] = ai;
    c[i] = b[i] - m * ai;
}

// ---------------- gather GEMM: g_h2[n,d] = sum_k sum_c relu(bn1(h1))[nbr[n,k],c] * W3[k,c,d] ----------------
__global__ __launch_bounds__(256) void k_gather(const int* __restrict__ nbr,
                                                const float* __restrict__ W3) {
    __shared__ float As[64 * PAD];
    __shared__ float Bs[64 * PAD];
    __shared__ int   sidx[64 * KNB];
    __shared__ float sa[MIDC], sc[MIDC];
    const int tid = threadIdx.x;
    const int p0  = blockIdx.x * 64;
    if (tid < MIDC) { sa[tid] = g_a1[tid]; sc[tid] = g_c1[tid]; }
    for (int i = tid; i < 64 * KNB; i += 256) sidx[i] = nbr[(size_t)p0 * KNB + i];
    const int row0 = (tid >> 4) << 2;
    const int col0 = (tid & 15) << 2;
    float acc[4][4] = {};

    for (int k = 0; k < KNB; k++) {
        __syncthreads();  // also covers the sidx/sa preload on the first iteration
        const float4* wb = (const float4*)(W3 + (size_t)k * MIDC * MIDC);
#pragma unroll
        for (int i = 0; i < 4; i++) {
            int j4 = tid + i * 256;
            int r = j4 >> 4, c = (j4 & 15) << 2;
            *(float4*)&Bs[r * PAD + c] = wb[j4];
            int ridx = sidx[r * KNB + k];
            float4 v = *(const float4*)&g_h1[(size_t)ridx * MIDC + c];
            v.x = fmaxf(fmaf(v.x, sa[c + 0], sc[c + 0]), 0.f);
            v.y = fmaxf(fmaf(v.y, sa[c + 1], sc[c + 1]), 0.f);
            v.z = fmaxf(fmaf(v.z, sa[c + 2], sc[c + 2]), 0.f);
            v.w = fmaxf(fmaf(v.w, sa[c + 3], sc[c + 3]), 0.f);
            *(float4*)&As[r * PAD + c] = v;
        }
        __syncthreads();
#pragma unroll 16
        for (int kk = 0; kk < 64; kk++) {
            float4 bv = *(float4*)&Bs[kk * PAD + col0];
            float a0 = As[(row0 + 0) * PAD + kk];
            float a1 = As[(row0 + 1) * PAD + kk];
            float a2 = As[(row0 + 2) * PAD + kk];
            float a3 = As[(row0 + 3) * PAD + kk];
            acc[0][0] = fmaf(a0, bv.x, acc[0][0]); acc[0][1] = fmaf(a0, bv.y, acc[0][1]);
            acc[0][2] = fmaf(a0, bv.z, acc[0][2]); acc[0][3] = fmaf(a0, bv.w, acc[0][3]);
            acc[1][0] = fmaf(a1, bv.x, acc[1][0]); acc[1][1] = fmaf(a1, bv.y, acc[1][1]);
            acc[1][2] = fmaf(a1, bv.z, acc[1][2]); acc[1][3] = fmaf(a1, bv.w, acc[1][3]);
            acc[2][0] = fmaf(a2, bv.x, acc[2][0]); acc[2][1] = fmaf(a2, bv.y, acc[2][1]);
            acc[2][2] = fmaf(a2, bv.z, acc[2][2]); acc[2][3] = fmaf(a2, bv.w, acc[2][3]);
            acc[3][0] = fmaf(a3, bv.x, acc[3][0]); acc[3][1] = fmaf(a3, bv.y, acc[3][1]);
            acc[3][2] = fmaf(a3, bv.z, acc[3][2]); acc[3][3] = fmaf(a3, bv.w, acc[3][3]);
        }
    }
#pragma unroll
    for (int i = 0; i < 4; i++)
        *(float4*)&g_h2[(size_t)(p0 + row0 + i) * MIDC + col0] =
            make_float4(acc[i][0], acc[i][1], acc[i][2], acc[i][3]);
}

// ---------------- GEMM2: g_h3 = relu(bn2(g_h2)) @ W2[64,256] ----------------
__global__ __launch_bounds__(256) void k_gemm2(const float* __restrict__ W2) {
    __shared__ float As[64 * PAD];
    __shared__ float Bs[64 * PAD];
    __shared__ float sa[MIDC], sc[MIDC];
    const int tid = threadIdx.x;
    const int p0  = blockIdx.x * 64;
    const int cb  = blockIdx.y * 64;
    if (tid < MIDC) { sa[tid] = g_a2[tid]; sc[tid] = g_c2[tid]; }
    __syncthreads();
#pragma unroll
    for (int i = 0; i < 4; i++) {
        int j4 = tid + i * 256;
        int r = j4 >> 4, c = (j4 & 15) << 2;
        float4 v = *(const float4*)&g_h2[(size_t)(p0 + r) * MIDC + c];
        v.x = fmaxf(fmaf(v.x, sa[c + 0], sc[c + 0]), 0.f);
        v.y = fmaxf(fmaf(v.y, sa[c + 1], sc[c + 1]), 0.f);
        v.z = fmaxf(fmaf(v.z, sa[c + 2], sc[c + 2]), 0.f);
        v.w = fmaxf(fmaf(v.w, sa[c + 3], sc[c + 3]), 0.f);
        *(float4*)&As[r * PAD + c] = v;
        float4 w = *(const float4*)(W2 + (size_t)r * OUTC + cb + c);
        *(float4*)&Bs[r * PAD + c] = w;
    }
    __syncthreads();
    const int row0 = (tid >> 4) << 2;
    const int col0 = (tid & 15) << 2;
    float acc[4][4] = {};
#pragma unroll 16
    for (int kk = 0; kk < 64; kk++) {
        float4 bv = *(float4*)&Bs[kk * PAD + col0];
        float a0 = As[(row0 + 0) * PAD + kk];
        float a1 = As[(row0 + 1) * PAD + kk];
        float a2 = As[(row0 + 2) * PAD + kk];
        float a3 = As[(row0 + 3) * PAD + kk];
        acc[0][0] = fmaf(a0, bv.x, acc[0][0]); acc[0][1] = fmaf(a0, bv.y, acc[0][1]);
        acc[0][2] = fmaf(a0, bv.z, acc[0][2]); acc[0][3] = fmaf(a0, bv.w, acc[0][3]);
        acc[1][0] = fmaf(a1, bv.x, acc[1][0]); acc[1][1] = fmaf(a1, bv.y, acc[1][1]);
        acc[1][2] = fmaf(a1, bv.z, acc[1][2]); acc[1][3] = fmaf(a1, bv.w, acc[1][3]);
        acc[2][0] = fmaf(a2, bv.x, acc[2][0]); acc[2][1] = fmaf(a2, bv.y, acc[2][1]);
        acc[2][2] = fmaf(a2, bv.z, acc[2][2]); acc[2][3] = fmaf(a2, bv.w, acc[2][3]);
        acc[3][0] = fmaf(a3, bv.x, acc[3][0]); acc[3][1] = fmaf(a3, bv.y, acc[3][1]);
        acc[3][2] = fmaf(a3, bv.z, acc[3][2]); acc[3][3] = fmaf(a3, bv.w, acc[3][3]);
    }
#pragma unroll
    for (int i = 0; i < 4; i++)
        *(float4*)&g_h3[(size_t)(p0 + row0 + i) * OUTC + cb + col0] =
            make_float4(acc[i][0], acc[i][1], acc[i][2], acc[i][3]);
}

// ---------------- epilogue: out = relu(bn3(h3) + x) ----------------
__global__ __launch_bounds__(256) void k_out(const float* __restrict__ x,
                                             float* __restrict__ out) {
    const size_t total4 = (size_t)NPTS * OUTC / 4;
    for (size_t i4 = (size_t)blockIdx.x * blockDim.x + threadIdx.x; i4 < total4;
         i4 += (size_t)gridDim.x * blockDim.x) {
        int c = (int)((i4 * 4) & (OUTC - 1));
        float4 h  = *(const float4*)&g_h3[i4 * 4];
        float4 xv = ((const float4*)x)[i4];
        float4 o;
        o.x = fmaxf(fmaf(h.x, g_a3[c + 0], g_c3[c + 0]) + xv.x, 0.f);
        o.y = fmaxf(fmaf(h.y, g_a3[c + 1], g_c3[c + 1]) + xv.y, 0.f);
        o.z = fmaxf(fmaf(h.z, g_a3[c + 2], g_c3[c + 2]) + xv.z, 0.f);
        o.w = fmaxf(fmaf(h.w, g_a3[c + 3], g_c3[c + 3]) + xv.w, 0.f);
        ((float4*)out)[i4] = o;
    }
}

// ---------------- launch ----------------
extern "C" void kernel_launch(void* const* d_in, const int* in_sizes, int n_in,
                              void* d_out, int out_size) {
    const float* x   = (const float*)d_in[0];
    const int*   nbr = (const int*)d_in[1];
    const float* W1  = (const float*)d_in[2];
    const float* W3  = (const float*)d_in[3];
    const float* W2  = (const float*)d_in[4];
    const float* g1  = (const float*)d_in[5];
    const float* b1  = (const float*)d_in[6];
    const float* g2  = (const float*)d_in[7];
    const float* b2  = (const float*)d_in[8];
    const float* g3  = (const float*)d_in[9];
    const float* b3  = (const float*)d_in[10];
    float* out = (float*)d_out;

    k_zero<<<1, 256>>>();
    k_gemm1<<<NPTS / 64, 256>>>(x, W1);
    k_stats_mid<<<512, 256>>>(0);
    k_finalize<<<1, 256>>>(g1, b1, 0);
    k_gather<<<NPTS / 64, 256>>>(nbr, W3);
    k_stats_mid<<<512, 256>>>(1);
    k_finalize<<<1, 256>>>(g2, b2, 1);
    dim3 grid2(NPTS / 64, 4);
    k_gemm2<<<grid2, 256>>>(W2);
    k_stats_out<<<512, 256>>>();
    k_finalize<<<1, 256>>>(g3, b3, 2);
    k_out<<<2048, 256>>>(x, out);
}

// round 2
// speedup vs baseline: 1.0689x; 1.0689x over previous
#include <cuda_runtime.h>

#define NPTS 120000
#define INC  256
#define MIDC 64
#define OUTC 256
#define KNB  27
#define EPSV 1e-5f
#define PAD  68   // floats per smem row: 272B = 16B*17 -> float4/ulonglong2 aligned, conflict-free

typedef unsigned long long u64;

// ---- f32x2 packed helpers (sm_103a) ----
__device__ __forceinline__ u64 pk2(float a) {
    u64 r; asm("mov.b64 %0,{%1,%1};" : "=l"(r) : "f"(a)); return r;
}
__device__ __forceinline__ void fma2(u64& d, u64 a, u64 b) {
    asm("fma.rn.f32x2 %0,%1,%2,%0;" : "+l"(d) : "l"(a), "l"(b));
}
__device__ __forceinline__ float2 up2(u64 v) {
    float2 r; asm("mov.b64 {%0,%1},%2;" : "=f"(r.x), "=f"(r.y) : "l"(v)); return r;
}

// ---------------- scratch ----------------
__device__ float g_h1[(size_t)NPTS * MIDC];
__device__ float g_h2[(size_t)NPTS * MIDC];
__device__ float g_h3[(size_t)NPTS * OUTC];
__device__ float g_sum1[MIDC], g_ssq1[MIDC], g_a1[MIDC], g_c1[MIDC];
__device__ float g_sum2[MIDC], g_ssq2[MIDC], g_a2[MIDC], g_c2[MIDC];
__device__ float g_sum3[OUTC], g_ssq3[OUTC], g_a3[OUTC], g_c3[OUTC];

__global__ void k_zero() {
    int t = threadIdx.x;
    if (t < MIDC) { g_sum1[t] = 0.f; g_ssq1[t] = 0.f; g_sum2[t] = 0.f; g_ssq2[t] = 0.f; }
    g_sum3[t] = 0.f; g_ssq3[t] = 0.f;
}

// 64-col block stats reduction: each thread holds 4x4 outputs (rows row0.., cols col0..)
// Reuses As/Bs smem. Adds partial column sums/ssq to gsum/gssq[colbase+col].
__device__ __forceinline__ void block_stats(float outf[4][4], float* As, float* Bs,
                                            int tid, int row0, int col0,
                                            float* gsum, float* gssq, int colbase) {
    float s[4], q[4];
#pragma unroll
    for (int j = 0; j < 4; j++) { s[j] = 0.f; q[j] = 0.f; }
#pragma unroll
    for (int i = 0; i < 4; i++)
#pragma unroll
        for (int j = 0; j < 4; j++) {
            float v = outf[i][j];
            s[j] += v; q[j] += v * v;
        }
    __syncthreads();
    int rg = tid >> 4;
#pragma unroll
    for (int j = 0; j < 4; j++) {
        As[rg * 64 + col0 + j] = s[j];
        Bs[rg * 64 + col0 + j] = q[j];
    }
    __syncthreads();
    if (tid < 64) {
        float S = 0.f, Q = 0.f;
#pragma unroll
        for (int g = 0; g < 16; g++) { S += As[g * 64 + tid]; Q += Bs[g * 64 + tid]; }
        atomicAdd(&gsum[colbase + tid], S);
        atomicAdd(&gssq[colbase + tid], Q);
    }
}

// ---------------- GEMM1: g_h1 = x[N,256] @ W1[256,64]; fused stats ----------------
__global__ __launch_bounds__(256) void k_gemm1(const float* __restrict__ x,
                                               const float* __restrict__ W1) {
    __shared__ float As[64 * PAD];
    __shared__ float Bs[64 * PAD];
    const int tid  = threadIdx.x;
    const int p0   = blockIdx.x * 64;
    const int row0 = (tid >> 4) << 2;
    const int col0 = (tid & 15) << 2;
    u64 acc[4][2] = {};

    for (int kc = 0; kc < 4; kc++) {
        __syncthreads();
#pragma unroll
        for (int i = 0; i < 4; i++) {
            int j4 = tid + i * 256;
            int r = j4 >> 4, c = (j4 & 15) << 2;
            *(float4*)&As[r * PAD + c] = *(const float4*)(x + (size_t)(p0 + r) * INC + kc * 64 + c);
            *(float4*)&Bs[r * PAD + c] = *(const float4*)(W1 + (size_t)(kc * 64 + r) * MIDC + c);
        }
        __syncthreads();
#pragma unroll 16
        for (int kk = 0; kk < 64; kk++) {
            ulonglong2 bv = *(const ulonglong2*)&Bs[kk * PAD + col0];
#pragma unroll
            for (int i = 0; i < 4; i++) {
                u64 av = pk2(As[(row0 + i) * PAD + kk]);
                fma2(acc[i][0], av, bv.x);
                fma2(acc[i][1], av, bv.y);
            }
        }
    }
    float outf[4][4];
#pragma unroll
    for (int i = 0; i < 4; i++) {
        float2 p = up2(acc[i][0]), q = up2(acc[i][1]);
        outf[i][0] = p.x; outf[i][1] = p.y; outf[i][2] = q.x; outf[i][3] = q.y;
        *(float4*)&g_h1[(size_t)(p0 + row0 + i) * MIDC + col0] = make_float4(p.x, p.y, q.x, q.y);
    }
    block_stats(outf, As, Bs, tid, row0, col0, g_sum1, g_ssq1, 0);
}

// ---------------- BN finalize ----------------
__global__ void k_finalize(const float* __restrict__ g, const float* __restrict__ b, int which) {
    int i = threadIdx.x;
    int C = (which == 2) ? OUTC : MIDC;
    if (i >= C) return;
    const float* sum = (which == 0) ? g_sum1 : (which == 1) ? g_sum2 : g_sum3;
    const float* ssq = (which == 0) ? g_ssq1 : (which == 1) ? g_ssq2 : g_ssq3;
    float* a = (which == 0) ? g_a1 : (which == 1) ? g_a2 : g_a3;
    float* c = (which == 0) ? g_c1 : (which == 1) ? g_c2 : g_c3;
    float m = sum[i] * (1.f / NPTS);
    float v = ssq[i] * (1.f / NPTS) - m * m;
    float ai = g[i] * rsqrtf(v + EPSV);
    a[i] = ai;
    c[i] = b[i] - m * ai;
}

// ---------------- gather GEMM + fused stats ----------------
__global__ __launch_bounds__(256) void k_gather(const int* __restrict__ nbr,
                                                const float* __restrict__ W3) {
    __shared__ float As[64 * PAD];
    __shared__ float Bs[64 * PAD];
    __shared__ int   sidx[64 * KNB];
    __shared__ float sa[MIDC], sc[MIDC];
    const int tid = threadIdx.x;
    const int p0  = blockIdx.x * 64;
    if (tid < MIDC) { sa[tid] = g_a1[tid]; sc[tid] = g_c1[tid]; }
    for (int i = tid; i < 64 * KNB; i += 256) sidx[i] = nbr[(size_t)p0 * KNB + i];
    const int row0 = (tid >> 4) << 2;
    const int col0 = (tid & 15) << 2;
    u64 acc[4][2] = {};

    for (int k = 0; k < KNB; k++) {
        __syncthreads();  // covers sidx/sa preload on first iter
        const float4* wb = (const float4*)(W3 + (size_t)k * MIDC * MIDC);
#pragma unroll
        for (int i = 0; i < 4; i++) {
            int j4 = tid + i * 256;
            int r = j4 >> 4, c = (j4 & 15) << 2;
            *(float4*)&Bs[r * PAD + c] = wb[j4];
            int ridx = sidx[r * KNB + k];
            float4 v = *(const float4*)&g_h1[(size_t)ridx * MIDC + c];
            v.x = fmaxf(fmaf(v.x, sa[c + 0], sc[c + 0]), 0.f);
            v.y = fmaxf(fmaf(v.y, sa[c + 1], sc[c + 1]), 0.f);
            v.z = fmaxf(fmaf(v.z, sa[c + 2], sc[c + 2]), 0.f);
            v.w = fmaxf(fmaf(v.w, sa[c + 3], sc[c + 3]), 0.f);
            *(float4*)&As[r * PAD + c] = v;
        }
        __syncthreads();
#pragma unroll 16
        for (int kk = 0; kk < 64; kk++) {
            ulonglong2 bv = *(const ulonglong2*)&Bs[kk * PAD + col0];
#pragma unroll
            for (int i = 0; i < 4; i++) {
                u64 av = pk2(As[(row0 + i) * PAD + kk]);
                fma2(acc[i][0], av, bv.x);
                fma2(acc[i][1], av, bv.y);
            }
        }
    }
    float outf[4][4];
#pragma unroll
    for (int i = 0; i < 4; i++) {
        float2 p = up2(acc[i][0]), q = up2(acc[i][1]);
        outf[i][0] = p.x; outf[i][1] = p.y; outf[i][2] = q.x; outf[i][3] = q.y;
        *(float4*)&g_h2[(size_t)(p0 + row0 + i) * MIDC + col0] = make_float4(p.x, p.y, q.x, q.y);
    }
    block_stats(outf, As, Bs, tid, row0, col0, g_sum2, g_ssq2, 0);
}

// ---------------- GEMM2: g_h3 = relu(bn2(g_h2)) @ W2[64,256]; fused stats ----------------
__global__ __launch_bounds__(256) void k_gemm2(const float* __restrict__ W2) {
    __shared__ float As[64 * PAD];
    __shared__ float Bs[64 * PAD];
    __shared__ float sa[MIDC], sc[MIDC];
    const int tid = threadIdx.x;
    const int p0  = blockIdx.x * 64;
    const int cb  = blockIdx.y * 64;
    if (tid < MIDC) { sa[tid] = g_a2[tid]; sc[tid] = g_c2[tid]; }
    __syncthreads();
#pragma unroll
    for (int i = 0; i < 4; i++) {
        int j4 = tid + i * 256;
        int r = j4 >> 4, c = (j4 & 15) << 2;
        float4 v = *(const float4*)&g_h2[(size_t)(p0 + r) * MIDC + c];
        v.x = fmaxf(fmaf(v.x, sa[c + 0], sc[c + 0]), 0.f);
        v.y = fmaxf(fmaf(v.y, sa[c + 1], sc[c + 1]), 0.f);
        v.z = fmaxf(fmaf(v.z, sa[c + 2], sc[c + 2]), 0.f);
        v.w = fmaxf(fmaf(v.w, sa[c + 3], sc[c + 3]), 0.f);
        *(float4*)&As[r * PAD + c] = v;
        *(float4*)&Bs[r * PAD + c] = *(const float4*)(W2 + (size_t)r * OUTC + cb + c);
    }
    __syncthreads();
    const int row0 = (tid >> 4) << 2;
    const int col0 = (tid & 15) << 2;
    u64 acc[4][2] = {};
#pragma unroll 16
    for (int kk = 0; kk < 64; kk++) {
        ulonglong2 bv = *(const ulonglong2*)&Bs[kk * PAD + col0];
#pragma unroll
        for (int i = 0; i < 4; i++) {
            u64 av = pk2(As[(row0 + i) * PAD + kk]);
            fma2(acc[i][0], av, bv.x);
            fma2(acc[i][1], av, bv.y);
        }
    }
    float outf[4][4];
#pragma unroll
    for (int i = 0; i < 4; i++) {
        float2 p = up2(acc[i][0]), q = up2(acc[i][1]);
        outf[i][0] = p.x; outf[i][1] = p.y; outf[i][2] = q.x; outf[i][3] = q.y;
        *(float4*)&g_h3[(size_t)(p0 + row0 + i) * OUTC + cb + col0] = make_float4(p.x, p.y, q.x, q.y);
    }
    block_stats(outf, As, Bs, tid, row0, col0, g_sum3, g_ssq3, cb);
}

// ---------------- epilogue: out = relu(bn3(h3) + x) ----------------
__global__ __launch_bounds__(256) void k_out(const float* __restrict__ x,
                                             float* __restrict__ out) {
    const size_t total4 = (size_t)NPTS * OUTC / 4;
    for (size_t i4 = (size_t)blockIdx.x * blockDim.x + threadIdx.x; i4 < total4;
         i4 += (size_t)gridDim.x * blockDim.x) {
        int c = (int)((i4 * 4) & (OUTC - 1));
        float4 h  = *(const float4*)&g_h3[i4 * 4];
        float4 xv = ((const float4*)x)[i4];
        float4 o;
        o.x = fmaxf(fmaf(h.x, g_a3[c + 0], g_c3[c + 0]) + xv.x, 0.f);
        o.y = fmaxf(fmaf(h.y, g_a3[c + 1], g_c3[c + 1]) + xv.y, 0.f);
        o.z = fmaxf(fmaf(h.z, g_a3[c + 2], g_c3[c + 2]) + xv.z, 0.f);
        o.w = fmaxf(fmaf(h.w, g_a3[c + 3], g_c3[c + 3]) + xv.w, 0.f);
        ((float4*)out)[i4] = o;
    }
}

// ---------------- launch ----------------
extern "C" void kernel_launch(void* const* d_in, const int* in_sizes, int n_in,
                              void* d_out, int out_size) {
    const float* x   = (const float*)d_in[0];
    const int*   nbr = (const int*)d_in[1];
    const float* W1  = (const float*)d_in[2];
    const float* W3  = (const float*)d_in[3];
    const float* W2  = (const float*)d_in[4];
    const float* g1  = (const float*)d_in[5];
    const float* b1  = (const float*)d_in[6];
    const float* g2  = (const float*)d_in[7];
    const float* b2  = (const float*)d_in[8];
    const float* g3  = (const float*)d_in[9];
    const float* b3  = (const float*)d_in[10];
    float* out = (float*)d_out;

    k_zero<<<1, 256>>>();
    k_gemm1<<<NPTS / 64, 256>>>(x, W1);
    k_finalize<<<1, 256>>>(g1, b1, 0);
    k_gather<<<NPTS / 64, 256>>>(nbr, W3);
    k_finalize<<<1, 256>>>(g2, b2, 1);
    dim3 grid2(NPTS / 64, 4);
    k_gemm2<<<grid2, 256>>>(W2);
    k_finalize<<<1, 256>>>(g3, b3, 2);
    k_out<<<2048, 256>>>(x, out);
}

// round 3
// speedup vs baseline: 1.2118x; 1.1337x over previous
#include <cuda_runtime.h>

#define NPTS 120000
#define INC  256
#define MIDC 64
#define OUTC 256
#define KNB  27
#define EPSV 1e-5f
#define PAD  68

typedef unsigned long long u64;

__device__ __forceinline__ u64 pk2(float a) {
    u64 r; asm("mov.b64 %0,{%1,%1};" : "=l"(r) : "f"(a)); return r;
}
__device__ __forceinline__ void fma2(u64& d, u64 a, u64 b) {
    asm("fma.rn.f32x2 %0,%1,%2,%0;" : "+l"(d) : "l"(a), "l"(b));
}
__device__ __forceinline__ float2 up2(u64 v) {
    float2 r; asm("mov.b64 {%0,%1},%2;" : "=f"(r.x), "=f"(r.y) : "l"(v)); return r;
}

// ---------------- scratch ----------------
__device__ float g_h1[(size_t)NPTS * MIDC];
__device__ float g_h2[(size_t)NPTS * MIDC];
__device__ float g_h3[(size_t)NPTS * OUTC];
__device__ float g_sum1[MIDC], g_ssq1[MIDC], g_a1[MIDC], g_c1[MIDC];
__device__ float g_sum2[MIDC], g_ssq2[MIDC], g_a2[MIDC], g_c2[MIDC];
__device__ float g_sum3[OUTC], g_ssq3[OUTC], g_a3[OUTC], g_c3[OUTC];

__global__ void k_zero() {
    int t = threadIdx.x;
    if (t < MIDC) { g_sum1[t] = 0.f; g_ssq1[t] = 0.f; g_sum2[t] = 0.f; g_ssq2[t] = 0.f; }
    g_sum3[t] = 0.f; g_ssq3[t] = 0.f;
}

// stats over a 128x64 block tile; each thread holds outf[8][4] (zeros for invalid rows)
__device__ __forceinline__ void block_stats8(float outf[8][4], float* As, float* Bs,
                                             int tid, int col0,
                                             float* gsum, float* gssq, int colbase) {
    float s[4] = {}, q[4] = {};
#pragma unroll
    for (int i = 0; i < 8; i++)
#pragma unroll
        for (int j = 0; j < 4; j++) { float v = outf[i][j]; s[j] += v; q[j] += v * v; }
    __syncthreads();
    int rg = tid >> 4;
#pragma unroll
    for (int j = 0; j < 4; j++) {
        As[rg * 64 + col0 + j] = s[j];
        Bs[rg * 64 + col0 + j] = q[j];
    }
    __syncthreads();
    if (tid < 64) {
        float S = 0.f, Q = 0.f;
#pragma unroll
        for (int g = 0; g < 16; g++) { S += As[g * 64 + tid]; Q += Bs[g * 64 + tid]; }
        atomicAdd(&gsum[colbase + tid], S);
        atomicAdd(&gssq[colbase + tid], Q);
    }
}

// shared inner product: acc[8][2] over 64-deep K tile, packed (kk even/odd in lanes resolved by caller? No)
// packing: acc pairs are (col0+0,col0+1) and (col0+2,col0+3)
__device__ __forceinline__ void mm_tile(const float* As, const float* Bs,
                                        int row0, int col0, u64 acc[8][2]) {
#pragma unroll 8
    for (int kk = 0; kk < 64; kk += 2) {
        ulonglong2 bv0 = *(const ulonglong2*)&Bs[kk * PAD + col0];
        ulonglong2 bv1 = *(const ulonglong2*)&Bs[(kk + 1) * PAD + col0];
#pragma unroll
        for (int i = 0; i < 8; i++) {
            float2 a = *(const float2*)&As[(row0 + i) * PAD + kk];
            u64 a0 = pk2(a.x), a1 = pk2(a.y);
            fma2(acc[i][0], a0, bv0.x);
            fma2(acc[i][1], a0, bv0.y);
            fma2(acc[i][0], a1, bv1.x);
            fma2(acc[i][1], a1, bv1.y);
        }
    }
}

// ---------------- GEMM1: g_h1 = x[N,256] @ W1[256,64]; fused stats ----------------
__global__ __launch_bounds__(256) void k_gemm1(const float* __restrict__ x,
                                               const float* __restrict__ W1) {
    extern __shared__ float smem[];
    float* As = smem;              // 128*PAD
    float* Bs = smem + 128 * PAD;  // 64*PAD
    const int tid  = threadIdx.x;
    const int p0   = blockIdx.x * 128;
    const int nval = (NPTS - p0 < 128) ? (NPTS - p0) : 128;
    const int row0 = (tid >> 4) << 3;
    const int col0 = (tid & 15) << 2;
    u64 acc[8][2] = {};

    for (int kc = 0; kc < 4; kc++) {
        __syncthreads();
#pragma unroll
        for (int i = 0; i < 8; i++) {
            int j4 = tid + i * 256;
            int r = j4 >> 4, c = (j4 & 15) << 2;
            int re = (r < nval) ? r : 0;
            *(float4*)&As[r * PAD + c] =
                *(const float4*)(x + (size_t)(p0 + re) * INC + kc * 64 + c);
        }
#pragma unroll
        for (int i = 0; i < 4; i++) {
            int j4 = tid + i * 256;
            int r = j4 >> 4, c = (j4 & 15) << 2;
            *(float4*)&Bs[r * PAD + c] = *(const float4*)(W1 + (size_t)(kc * 64 + r) * MIDC + c);
        }
        __syncthreads();
        mm_tile(As, Bs, row0, col0, acc);
    }
    float outf[8][4];
#pragma unroll
    for (int i = 0; i < 8; i++) {
        float2 p = up2(acc[i][0]), q = up2(acc[i][1]);
        bool v = (row0 + i) < nval;
        outf[i][0] = v ? p.x : 0.f; outf[i][1] = v ? p.y : 0.f;
        outf[i][2] = v ? q.x : 0.f; outf[i][3] = v ? q.y : 0.f;
        if (v)
            *(float4*)&g_h1[(size_t)(p0 + row0 + i) * MIDC + col0] =
                make_float4(p.x, p.y, q.x, q.y);
    }
    block_stats8(outf, As, Bs, tid, col0, g_sum1, g_ssq1, 0);
}

// ---------------- BN finalize ----------------
__global__ void k_finalize(const float* __restrict__ g, const float* __restrict__ b, int which) {
    int i = threadIdx.x;
    int C = (which == 2) ? OUTC : MIDC;
    if (i >= C) return;
    const float* sum = (which == 0) ? g_sum1 : (which == 1) ? g_sum2 : g_sum3;
    const float* ssq = (which == 0) ? g_ssq1 : (which == 1) ? g_ssq2 : g_ssq3;
    float* a = (which == 0) ? g_a1 : (which == 1) ? g_a2 : g_a3;
    float* c = (which == 0) ? g_c1 : (which == 1) ? g_c2 : g_c3;
    float m = sum[i] * (1.f / NPTS);
    float v = ssq[i] * (1.f / NPTS) - m * m;
    float ai = g[i] * rsqrtf(v + EPSV);
    a[i] = ai;
    c[i] = b[i] - m * ai;
}

// ---------------- gather GEMM + fused stats ----------------
__global__ __launch_bounds__(256) void k_gather(const int* __restrict__ nbr,
                                                const float* __restrict__ W3) {
    extern __shared__ float smem[];
    float* As = smem;                       // 128*PAD
    float* Bs = smem + 128 * PAD;           // 64*PAD
    int*   sidx = (int*)(smem + 192 * PAD); // 128*KNB
    float* sa = (float*)(sidx + 128 * KNB);
    float* sc = sa + MIDC;
    const int tid = threadIdx.x;
    const int p0  = blockIdx.x * 128;
    const int nval = (NPTS - p0 < 128) ? (NPTS - p0) : 128;
    if (tid < MIDC) { sa[tid] = g_a1[tid]; sc[tid] = g_c1[tid]; }
    for (int i = tid; i < nval * KNB; i += 256) sidx[i] = nbr[(size_t)p0 * KNB + i];
    const int row0 = (tid >> 4) << 3;
    const int col0 = (tid & 15) << 2;
    u64 acc[8][2] = {};

    for (int k = 0; k < KNB; k++) {
        __syncthreads();  // also covers sidx/sa preload on first iter
        const float4* wb = (const float4*)(W3 + (size_t)k * MIDC * MIDC);
#pragma unroll
        for (int i = 0; i < 4; i++) {
            int j4 = tid + i * 256;
            int r = j4 >> 4, c = (j4 & 15) << 2;
            *(float4*)&Bs[r * PAD + c] = wb[j4];
        }
#pragma unroll
        for (int i = 0; i < 8; i++) {
            int j4 = tid + i * 256;
            int r = j4 >> 4, c = (j4 & 15) << 2;
            int ridx = (r < nval) ? sidx[r * KNB + k] : 0;
            float4 v = *(const float4*)&g_h1[(size_t)ridx * MIDC + c];
            v.x = fmaxf(fmaf(v.x, sa[c + 0], sc[c + 0]), 0.f);
            v.y = fmaxf(fmaf(v.y, sa[c + 1], sc[c + 1]), 0.f);
            v.z = fmaxf(fmaf(v.z, sa[c + 2], sc[c + 2]), 0.f);
            v.w = fmaxf(fmaf(v.w, sa[c + 3], sc[c + 3]), 0.f);
            *(float4*)&As[r * PAD + c] = v;
        }
        __syncthreads();
        mm_tile(As, Bs, row0, col0, acc);
    }
    float outf[8][4];
#pragma unroll
    for (int i = 0; i < 8; i++) {
        float2 p = up2(acc[i][0]), q = up2(acc[i][1]);
        bool v = (row0 + i) < nval;
        outf[i][0] = v ? p.x : 0.f; outf[i][1] = v ? p.y : 0.f;
        outf[i][2] = v ? q.x : 0.f; outf[i][3] = v ? q.y : 0.f;
        if (v)
            *(float4*)&g_h2[(size_t)(p0 + row0 + i) * MIDC + col0] =
                make_float4(p.x, p.y, q.x, q.y);
    }
    block_stats8(outf, As, Bs, tid, col0, g_sum2, g_ssq2, 0);
}

// ---------------- GEMM2: g_h3 = relu(bn2(g_h2)) @ W2[64,256]; fused stats ----------------
__global__ __launch_bounds__(256) void k_gemm2(const float* __restrict__ W2) {
    extern __shared__ float smem[];
    float* As = smem;
    float* Bs = smem + 128 * PAD;
    float* sa = smem + 192 * PAD;
    float* sc = sa + MIDC;
    const int tid = threadIdx.x;
    const int p0  = blockIdx.x * 128;
    const int cb  = blockIdx.y * 64;
    const int nval = (NPTS - p0 < 128) ? (NPTS - p0) : 128;
    if (tid < MIDC) { sa[tid] = g_a2[tid]; sc[tid] = g_c2[tid]; }
    __syncthreads();
#pragma unroll
    for (int i = 0; i < 8; i++) {
        int j4 = tid + i * 256;
        int r = j4 >> 4, c = (j4 & 15) << 2;
        int re = (r < nval) ? r : 0;
        float4 v = *(const float4*)&g_h2[(size_t)(p0 + re) * MIDC + c];
        v.x = fmaxf(fmaf(v.x, sa[c + 0], sc[c + 0]), 0.f);
        v.y = fmaxf(fmaf(v.y, sa[c + 1], sc[c + 1]), 0.f);
        v.z = fmaxf(fmaf(v.z, sa[c + 2], sc[c + 2]), 0.f);
        v.w = fmaxf(fmaf(v.w, sa[c + 3], sc[c + 3]), 0.f);
        *(float4*)&As[r * PAD + c] = v;
    }
#pragma unroll
    for (int i = 0; i < 4; i++) {
        int j4 = tid + i * 256;
        int r = j4 >> 4, c = (j4 & 15) << 2;
        *(float4*)&Bs[r * PAD + c] = *(const float4*)(W2 + (size_t)r * OUTC + cb + c);
    }
    __syncthreads();
    const int row0 = (tid >> 4) << 3;
    const int col0 = (tid & 15) << 2;
    u64 acc[8][2] = {};
    mm_tile(As, Bs, row0, col0, acc);

    float outf[8][4];
#pragma unroll
    for (int i = 0; i < 8; i++) {
        float2 p = up2(acc[i][0]), q = up2(acc[i][1]);
        bool v = (row0 + i) < nval;
        outf[i][0] = v ? p.x : 0.f; outf[i][1] = v ? p.y : 0.f;
        outf[i][2] = v ? q.x : 0.f; outf[i][3] = v ? q.y : 0.f;
        if (v)
            *(float4*)&g_h3[(size_t)(p0 + row0 + i) * OUTC + cb + col0] =
                make_float4(p.x, p.y, q.x, q.y);
    }
    block_stats8(outf, As, Bs, tid, col0, g_sum3, g_ssq3, cb);
}

// ---------------- epilogue: out = relu(bn3(h3) + x) ----------------
__global__ __launch_bounds__(256) void k_out(const float* __restrict__ x,
                                             float* __restrict__ out) {
    const size_t total4 = (size_t)NPTS * OUTC / 4;
    for (size_t i4 = (size_t)blockIdx.x * blockDim.x + threadIdx.x; i4 < total4;
         i4 += (size_t)gridDim.x * blockDim.x) {
        int c = (int)((i4 * 4) & (OUTC - 1));
        float4 h  = *(const float4*)&g_h3[i4 * 4];
        float4 xv = ((const float4*)x)[i4];
        float4 o;
        o.x = fmaxf(fmaf(h.x, g_a3[c + 0], g_c3[c + 0]) + xv.x, 0.f);
        o.y = fmaxf(fmaf(h.y, g_a3[c + 1], g_c3[c + 1]) + xv.y, 0.f);
        o.z = fmaxf(fmaf(h.z, g_a3[c + 2], g_c3[c + 2]) + xv.z, 0.f);
        o.w = fmaxf(fmaf(h.w, g_a3[c + 3], g_c3[c + 3]) + xv.w, 0.f);
        ((float4*)out)[i4] = o;
    }
}

// ---------------- launch ----------------
extern "C" void kernel_launch(void* const* d_in, const int* in_sizes, int n_in,
                              void* d_out, int out_size) {
    const float* x   = (const float*)d_in[0];
    const int*   nbr = (const int*)d_in[1];
    const float* W1  = (const float*)d_in[2];
    const float* W3  = (const float*)d_in[3];
    const float* W2  = (const float*)d_in[4];
    const float* g1  = (const float*)d_in[5];
    const float* b1  = (const float*)d_in[6];
    const float* g2  = (const float*)d_in[7];
    const float* b2  = (const float*)d_in[8];
    const float* g3  = (const float*)d_in[9];
    const float* b3  = (const float*)d_in[10];
    float* out = (float*)d_out;

    const int SM_G12 = 192 * PAD * 4 + 2 * MIDC * 4;                 // gemm1/gemm2
    const int SM_GAT = 192 * PAD * 4 + 128 * KNB * 4 + 2 * MIDC * 4; // gather
    static bool attr_done = false;
    if (!attr_done) {
        cudaFuncSetAttribute(k_gemm1, cudaFuncAttributeMaxDynamicSharedMemorySize, SM_G12);
        cudaFuncSetAttribute(k_gather, cudaFuncAttributeMaxDynamicSharedMemorySize, SM_GAT);
        cudaFuncSetAttribute(k_gemm2, cudaFuncAttributeMaxDynamicSharedMemorySize, SM_G12);
        attr_done = true;
    }

    const int GB = (NPTS + 127) / 128;  // 938
    k_zero<<<1, 256>>>();
    k_gemm1<<<GB, 256, SM_G12>>>(x, W1);
    k_finalize<<<1, 256>>>(g1, b1, 0);
    k_gather<<<GB, 256, SM_GAT>>>(nbr, W3);
    k_finalize<<<1, 256>>>(g2, b2, 1);
    dim3 grid2(GB, 4);
    k_gemm2<<<grid2, 256, SM_G12>>>(W2);
    k_finalize<<<1, 256>>>(g3, b3, 2);
    k_out<<<2048, 256>>>(x, out);
}

// round 4
// speedup vs baseline: 1.2567x; 1.0370x over previous
#include <cuda_runtime.h>

#define NPTS 120000
#define INC  256
#define MIDC 64
#define OUTC 256
#define KNB  27
#define EPSV 1e-5f

typedef unsigned long long u64;
typedef unsigned int u32;

// ---- f32x2 packed helpers (sm_103a) ----
__device__ __forceinline__ u64 pk2(float a) {
    u64 r; asm("mov.b64 %0,{%1,%1};" : "=l"(r) : "f"(a)); return r;
}
__device__ __forceinline__ void fma2(u64& d, u64 a, u64 b) {
    asm("fma.rn.f32x2 %0,%1,%2,%0;" : "+l"(d) : "l"(a), "l"(b));
}
__device__ __forceinline__ float2 up2(u64 v) {
    float2 r; asm("mov.b64 {%0,%1},%2;" : "=f"(r.x), "=f"(r.y) : "l"(v)); return r;
}

// ---- cp.async helpers ----
__device__ __forceinline__ u32 sptr(const void* p) { return (u32)__cvta_generic_to_shared(p); }
__device__ __forceinline__ void cpa16(u32 d, const void* s) {
    asm volatile("cp.async.ca.shared.global [%0],[%1],16;" :: "r"(d), "l"(s));
}
__device__ __forceinline__ void cpa_commit() { asm volatile("cp.async.commit_group;"); }
template<int N> __device__ __forceinline__ void cpa_wait() {
    asm volatile("cp.async.wait_group %0;" :: "n"(N));
}

// ---------------- scratch ----------------
__device__ float g_h1[(size_t)NPTS * MIDC];
__device__ float g_r1[(size_t)NPTS * MIDC];   // relu(bn1(h1))
__device__ float g_h2[(size_t)NPTS * MIDC];
__device__ float g_h3[(size_t)NPTS * OUTC];
__device__ float g_sum1[MIDC], g_ssq1[MIDC], g_a1[MIDC], g_c1[MIDC];
__device__ float g_sum2[MIDC], g_ssq2[MIDC], g_a2[MIDC], g_c2[MIDC];
__device__ float g_sum3[OUTC], g_ssq3[OUTC], g_a3[OUTC], g_c3[OUTC];

__global__ void k_zero() {
    int t = threadIdx.x;
    if (t < MIDC) { g_sum1[t] = 0.f; g_ssq1[t] = 0.f; g_sum2[t] = 0.f; g_ssq2[t] = 0.f; }
    g_sum3[t] = 0.f; g_ssq3[t] = 0.f;
}

// stats over a 128x64 block tile (outf zeros for invalid rows); s0/s1 = >=1024-float smem scratch
__device__ __forceinline__ void block_stats8(float outf[8][4], float* s0, float* s1,
                                             int tid, int col0,
                                             float* gsum, float* gssq, int colbase) {
    float s[4] = {}, q[4] = {};
#pragma unroll
    for (int i = 0; i < 8; i++)
#pragma unroll
        for (int j = 0; j < 4; j++) { float v = outf[i][j]; s[j] += v; q[j] += v * v; }
    __syncthreads();
    int rg = tid >> 4;
#pragma unroll
    for (int j = 0; j < 4; j++) {
        s0[rg * 64 + col0 + j] = s[j];
        s1[rg * 64 + col0 + j] = q[j];
    }
    __syncthreads();
    if (tid < 64) {
        float S = 0.f, Q = 0.f;
#pragma unroll
        for (int g = 0; g < 16; g++) { S += s0[g * 64 + tid]; Q += s1[g * 64 + tid]; }
        atomicAdd(&gsum[colbase + tid], S);
        atomicAdd(&gssq[colbase + tid], Q);
    }
}

// 128x64 += 128x64 @ 64x64, stride-64 smem tiles (conflict-free for this pattern)
__device__ __forceinline__ void mm_tile64(const float* As, const float* Bs,
                                          int row0, int col0, u64 acc[8][2]) {
#pragma unroll 8
    for (int kk = 0; kk < 64; kk += 2) {
        ulonglong2 bv0 = *(const ulonglong2*)&Bs[kk * 64 + col0];
        ulonglong2 bv1 = *(const ulonglong2*)&Bs[(kk + 1) * 64 + col0];
#pragma unroll
        for (int i = 0; i < 8; i++) {
            float2 a = *(const float2*)&As[(row0 + i) * 64 + kk];
            u64 a0 = pk2(a.x), a1 = pk2(a.y);
            fma2(acc[i][0], a0, bv0.x);
            fma2(acc[i][1], a0, bv0.y);
            fma2(acc[i][0], a1, bv1.x);
            fma2(acc[i][1], a1, bv1.y);
        }
    }
}

// ---------------- GEMM1: g_h1 = x[N,256] @ W1[256,64]; cp.async pipelined; fused stats ----------------
__global__ __launch_bounds__(256) void k_gemm1(const float* __restrict__ x,
                                               const float* __restrict__ W1) {
    extern __shared__ float smem[];
    float* As = smem;               // 2 * 128*64
    float* Bs = smem + 2 * 128 * 64; // 2 * 64*64
    const int tid  = threadIdx.x;
    const int p0   = blockIdx.x * 128;
    const int nval = (NPTS - p0 < 128) ? (NPTS - p0) : 128;
    const int row0 = (tid >> 4) << 3;
    const int col0 = (tid & 15) << 2;
    u64 acc[8][2] = {};

    auto issue = [&](int kc, int buf) {
        float* Ad = As + buf * 8192;
        float* Bd = Bs + buf * 4096;
#pragma unroll
        for (int i = 0; i < 8; i++) {
            int j4 = tid + i * 256;
            int r = j4 >> 4, c = (j4 & 15) << 2;
            int re = (r < nval) ? r : 0;
            cpa16(sptr(&Ad[r * 64 + c]), x + (size_t)(p0 + re) * INC + kc * 64 + c);
        }
#pragma unroll
        for (int i = 0; i < 4; i++) {
            int j4 = tid + i * 256;
            int r = j4 >> 4, c = (j4 & 15) << 2;
            cpa16(sptr(&Bd[r * 64 + c]), W1 + (size_t)(kc * 64 + r) * MIDC + c);
        }
        cpa_commit();
    };

    issue(0, 0);
    for (int kc = 0; kc < 4; kc++) {
        int cur = kc & 1;
        if (kc + 1 < 4) { issue(kc + 1, cur ^ 1); cpa_wait<1>(); }
        else cpa_wait<0>();
        __syncthreads();
        mm_tile64(As + cur * 8192, Bs + cur * 4096, row0, col0, acc);
        __syncthreads();
    }

    float outf[8][4];
#pragma unroll
    for (int i = 0; i < 8; i++) {
        float2 p = up2(acc[i][0]), q = up2(acc[i][1]);
        bool v = (row0 + i) < nval;
        outf[i][0] = v ? p.x : 0.f; outf[i][1] = v ? p.y : 0.f;
        outf[i][2] = v ? q.x : 0.f; outf[i][3] = v ? q.y : 0.f;
        if (v)
            *(float4*)&g_h1[(size_t)(p0 + row0 + i) * MIDC + col0] =
                make_float4(p.x, p.y, q.x, q.y);
    }
    block_stats8(outf, As, Bs, tid, col0, g_sum1, g_ssq1, 0);
}

// ---------------- BN finalize ----------------
__global__ void k_finalize(const float* __restrict__ g, const float* __restrict__ b, int which) {
    int i = threadIdx.x;
    int C = (which == 2) ? OUTC : MIDC;
    if (i >= C) return;
    const float* sum = (which == 0) ? g_sum1 : (which == 1) ? g_sum2 : g_sum3;
    const float* ssq = (which == 0) ? g_ssq1 : (which == 1) ? g_ssq2 : g_ssq3;
    float* a = (which == 0) ? g_a1 : (which == 1) ? g_a2 : g_a3;
    float* c = (which == 0) ? g_c1 : (which == 1) ? g_c2 : g_c3;
    float m = sum[i] * (1.f / NPTS);
    float v = ssq[i] * (1.f / NPTS) - m * m;
    float ai = g[i] * rsqrtf(v + EPSV);
    a[i] = ai;
    c[i] = b[i] - m * ai;
}

// ---------------- norm1: g_r1 = relu(bn1(g_h1)) ----------------
__global__ __launch_bounds__(256) void k_norm1() {
    const size_t total4 = (size_t)NPTS * MIDC / 4;
    for (size_t i4 = (size_t)blockIdx.x * blockDim.x + threadIdx.x; i4 < total4;
         i4 += (size_t)gridDim.x * blockDim.x) {
        int c = (int)((i4 * 4) & (MIDC - 1));
        float4 v = *(const float4*)&g_h1[i4 * 4];
        v.x = fmaxf(fmaf(v.x, g_a1[c + 0], g_c1[c + 0]), 0.f);
        v.y = fmaxf(fmaf(v.y, g_a1[c + 1], g_c1[c + 1]), 0.f);
        v.z = fmaxf(fmaf(v.z, g_a1[c + 2], g_c1[c + 2]), 0.f);
        v.w = fmaxf(fmaf(v.w, g_a1[c + 3], g_c1[c + 3]), 0.f);
        *(float4*)&g_r1[i4 * 4] = v;
    }
}

// ---------------- gather GEMM (cp.async pipelined) + fused stats ----------------
__global__ __launch_bounds__(256) void k_gather(const int* __restrict__ nbr,
                                                const float* __restrict__ W3) {
    extern __shared__ float smem[];
    float* As = smem;                      // 2 * 128*64
    float* Bs = smem + 2 * 128 * 64;       // 2 * 64*64
    int*   sidx = (int*)(smem + 2 * 128 * 64 + 2 * 64 * 64); // 128*KNB
    const int tid = threadIdx.x;
    const int p0  = blockIdx.x * 128;
    const int nval = (NPTS - p0 < 128) ? (NPTS - p0) : 128;
    const int row0 = (tid >> 4) << 3;
    const int col0 = (tid & 15) << 2;

    for (int i = tid; i < nval * KNB; i += 256) sidx[i] = nbr[(size_t)p0 * KNB + i];
    __syncthreads();

    auto issue = [&](int k, int buf) {
        float* Bd = Bs + buf * 4096;
        const float* wb = W3 + (size_t)k * MIDC * MIDC;
#pragma unroll
        for (int i = 0; i < 4; i++) {
            int j4 = tid + i * 256;
            int r = j4 >> 4, c = (j4 & 15) << 2;
            cpa16(sptr(&Bd[r * 64 + c]), wb + r * 64 + c);
        }
        float* Ad = As + buf * 8192;
#pragma unroll
        for (int i = 0; i < 8; i++) {
            int j4 = tid + i * 256;
            int r = j4 >> 4, c = (j4 & 15) << 2;
            int ridx = (r < nval) ? sidx[r * KNB + k] : 0;
            cpa16(sptr(&Ad[r * 64 + c]), g_r1 + (size_t)ridx * MIDC + c);
        }
        cpa_commit();
    };

    u64 acc[8][2] = {};
    issue(0, 0);
    for (int k = 0; k < KNB; k++) {
        int cur = k & 1;
        if (k + 1 < KNB) { issue(k + 1, cur ^ 1); cpa_wait<1>(); }
        else cpa_wait<0>();
        __syncthreads();
        mm_tile64(As + cur * 8192, Bs + cur * 4096, row0, col0, acc);
        __syncthreads();
    }

    float outf[8][4];
#pragma unroll
    for (int i = 0; i < 8; i++) {
        float2 p = up2(acc[i][0]), q = up2(acc[i][1]);
        bool v = (row0 + i) < nval;
        outf[i][0] = v ? p.x : 0.f; outf[i][1] = v ? p.y : 0.f;
        outf[i][2] = v ? q.x : 0.f; outf[i][3] = v ? q.y : 0.f;
        if (v)
            *(float4*)&g_h2[(size_t)(p0 + row0 + i) * MIDC + col0] =
                make_float4(p.x, p.y, q.x, q.y);
    }
    block_stats8(outf, As, Bs, tid, col0, g_sum2, g_ssq2, 0);
}

// ---------------- GEMM2: g_h3 = relu(bn2(g_h2)) @ W2[64,256]; fused stats ----------------
__global__ __launch_bounds__(256) void k_gemm2(const float* __restrict__ W2) {
    extern __shared__ float smem[];
    float* As = smem;             // 128*64
    float* Bs = smem + 128 * 64;  // 64*64
    float* sa = smem + 192 * 64;
    float* sc = sa + MIDC;
    const int tid = threadIdx.x;
    const int p0  = blockIdx.x * 128;
    const int cb  = blockIdx.y * 64;
    const int nval = (NPTS - p0 < 128) ? (NPTS - p0) : 128;
    if (tid < MIDC) { sa[tid] = g_a2[tid]; sc[tid] = g_c2[tid]; }
    __syncthreads();
#pragma unroll
    for (int i = 0; i < 8; i++) {
        int j4 = tid + i * 256;
        int r = j4 >> 4, c = (j4 & 15) << 2;
        int re = (r < nval) ? r : 0;
        float4 v = *(const float4*)&g_h2[(size_t)(p0 + re) * MIDC + c];
        v.x = fmaxf(fmaf(v.x, sa[c + 0], sc[c + 0]), 0.f);
        v.y = fmaxf(fmaf(v.y, sa[c + 1], sc[c + 1]), 0.f);
        v.z = fmaxf(fmaf(v.z, sa[c + 2], sc[c + 2]), 0.f);
        v.w = fmaxf(fmaf(v.w, sa[c + 3], sc[c + 3]), 0.f);
        *(float4*)&As[r * 64 + c] = v;
    }
#pragma unroll
    for (int i = 0; i < 4; i++) {
        int j4 = tid + i * 256;
        int r = j4 >> 4, c = (j4 & 15) << 2;
        *(float4*)&Bs[r * 64 + c] = *(const float4*)(W2 + (size_t)r * OUTC + cb + c);
    }
    __syncthreads();
    const int row0 = (tid >> 4) << 3;
    const int col0 = (tid & 15) << 2;
    u64 acc[8][2] = {};
    mm_tile64(As, Bs, row0, col0, acc);

    float outf[8][4];
#pragma unroll
    for (int i = 0; i < 8; i++) {
        float2 p = up2(acc[i][0]), q = up2(acc[i][1]);
        bool v = (row0 + i) < nval;
        outf[i][0] = v ? p.x : 0.f; outf[i][1] = v ? p.y : 0.f;
        outf[i][2] = v ? q.x : 0.f; outf[i][3] = v ? q.y : 0.f;
        if (v)
            *(float4*)&g_h3[(size_t)(p0 + row0 + i) * OUTC + cb + col0] =
                make_float4(p.x, p.y, q.x, q.y);
    }
    block_stats8(outf, As, Bs, tid, col0, g_sum3, g_ssq3, cb);
}

// ---------------- epilogue: out = relu(bn3(h3) + x) ----------------
__global__ __launch_bounds__(256) void k_out(const float* __restrict__ x,
                                             float* __restrict__ out) {
    const size_t total4 = (size_t)NPTS * OUTC / 4;
    for (size_t i4 = (size_t)blockIdx.x * blockDim.x + threadIdx.x; i4 < total4;
         i4 += (size_t)gridDim.x * blockDim.x) {
        int c = (int)((i4 * 4) & (OUTC - 1));
        float4 h  = *(const float4*)&g_h3[i4 * 4];
        float4 xv = ((const float4*)x)[i4];
        float4 o;
        o.x = fmaxf(fmaf(h.x, g_a3[c + 0], g_c3[c + 0]) + xv.x, 0.f);
        o.y = fmaxf(fmaf(h.y, g_a3[c + 1], g_c3[c + 1]) + xv.y, 0.f);
        o.z = fmaxf(fmaf(h.z, g_a3[c + 2], g_c3[c + 2]) + xv.z, 0.f);
        o.w = fmaxf(fmaf(h.w, g_a3[c + 3], g_c3[c + 3]) + xv.w, 0.f);
        ((float4*)out)[i4] = o;
    }
}

// ---------------- launch ----------------
extern "C" void kernel_launch(void* const* d_in, const int* in_sizes, int n_in,
                              void* d_out, int out_size) {
    const float* x   = (const float*)d_in[0];
    const int*   nbr = (const int*)d_in[1];
    const float* W1  = (const float*)d_in[2];
    const float* W3  = (const float*)d_in[3];
    const float* W2  = (const float*)d_in[4];
    const float* g1  = (const float*)d_in[5];
    const float* b1  = (const float*)d_in[6];
    const float* g2  = (const float*)d_in[7];
    const float* b2  = (const float*)d_in[8];
    const float* g3  = (const float*)d_in[9];
    const float* b3  = (const float*)d_in[10];
    float* out = (float*)d_out;

    const int SM_G1  = (2 * 128 * 64 + 2 * 64 * 64) * 4;                  // 96 KB
    const int SM_GAT = SM_G1 + 128 * KNB * 4;                             // ~109.5 KB
    const int SM_G2  = (128 * 64 + 64 * 64) * 4 + 2 * MIDC * 4;           // ~48.5 KB
    static bool attr_done = false;
    if (!attr_done) {
        cudaFuncSetAttribute(k_gemm1, cudaFuncAttributeMaxDynamicSharedMemorySize, SM_G1);
        cudaFuncSetAttribute(k_gather, cudaFuncAttributeMaxDynamicSharedMemorySize, SM_GAT);
        cudaFuncSetAttribute(k_gemm2, cudaFuncAttributeMaxDynamicSharedMemorySize, SM_G2);
        attr_done = true;
    }

    const int GB = (NPTS + 127) / 128;  // 938
    k_zero<<<1, 256>>>();
    k_gemm1<<<GB, 256, SM_G1>>>(x, W1);
    k_finalize<<<1, 256>>>(g1, b1, 0);
    k_norm1<<<2048, 256>>>();
    k_gather<<<GB, 256, SM_GAT>>>(nbr, W3);
    k_finalize<<<1, 256>>>(g2, b2, 1);
    dim3 grid2(GB, 4);
    k_gemm2<<<grid2, 256, SM_G2>>>(W2);
    k_finalize<<<1, 256>>>(g3, b3, 2);
    k_out<<<2048, 256>>>(x, out);
}

// round 6
// speedup vs baseline: 1.2754x; 1.0149x over previous
#include <cuda_runtime.h>

#define NPTS 120000
#define INC  256
#define MIDC 64
#define OUTC 256
#define KNB  27
#define EPSV 1e-5f
#define PADK 68   // smem row stride for mma-fragment tiles (bank-conflict-free)

typedef unsigned long long u64;
typedef unsigned int u32;

// ---- f32x2 packed helpers ----
__device__ __forceinline__ u64 pk2(float a) {
    u64 r; asm("mov.b64 %0,{%1,%1};" : "=l"(r) : "f"(a)); return r;
}
__device__ __forceinline__ void fma2(u64& d, u64 a, u64 b) {
    asm("fma.rn.f32x2 %0,%1,%2,%0;" : "+l"(d) : "l"(a), "l"(b));
}
__device__ __forceinline__ float2 up2(u64 v) {
    float2 r; asm("mov.b64 {%0,%1},%2;" : "=f"(r.x), "=f"(r.y) : "l"(v)); return r;
}

// ---- cp.async helpers ----
__device__ __forceinline__ u32 sptr(const void* p) { return (u32)__cvta_generic_to_shared(p); }
__device__ __forceinline__ void cpa16(u32 d, const void* s) {
    asm volatile("cp.async.ca.shared.global [%0],[%1],16;" :: "r"(d), "l"(s));
}
__device__ __forceinline__ void cpa_commit() { asm volatile("cp.async.commit_group;"); }
template<int N> __device__ __forceinline__ void cpa_wait() {
    asm volatile("cp.async.wait_group %0;" :: "n"(N));
}

// ---- tf32 mma: D[16x8] += A[16x8] * B[8x8] (row.col) ----
__device__ __forceinline__ void mma_tf32(float d[4], u32 a0, u32 a1, u32 a2, u32 a3,
                                         u32 b0, u32 b1) {
    asm volatile(
        "mma.sync.aligned.m16n8k8.row.col.f32.tf32.tf32.f32 "
        "{%0,%1,%2,%3},{%4,%5,%6,%7},{%8,%9},{%0,%1,%2,%3};"
        : "+f"(d[0]), "+f"(d[1]), "+f"(d[2]), "+f"(d[3])
        : "r"(a0), "r"(a1), "r"(a2), "r"(a3), "r"(b0), "r"(b1));
}

// ---------------- scratch ----------------
__device__ float g_h1[(size_t)NPTS * MIDC];
__device__ float g_r1[(size_t)NPTS * MIDC];
__device__ float g_h2[(size_t)NPTS * MIDC];
__device__ float g_h3[(size_t)NPTS * OUTC];
__device__ float g_sum1[MIDC], g_ssq1[MIDC], g_a1[MIDC], g_c1[MIDC];
__device__ float g_sum2[MIDC], g_ssq2[MIDC], g_a2[MIDC], g_c2[MIDC];
__device__ float g_sum3[OUTC], g_ssq3[OUTC], g_a3[OUTC], g_c3[OUTC];

__global__ void k_zero() {
    int t = threadIdx.x;
    if (t < MIDC) { g_sum1[t] = 0.f; g_ssq1[t] = 0.f; g_sum2[t] = 0.f; g_ssq2[t] = 0.f; }
    g_sum3[t] = 0.f; g_ssq3[t] = 0.f;
}

// stats over a 128x64 block tile (outf zeros for invalid rows)
__device__ __forceinline__ void block_stats8(float outf[8][4], float* s0, float* s1,
                                             int tid, int col0,
                                             float* gsum, float* gssq, int colbase) {
    float s[4] = {}, q[4] = {};
#pragma unroll
    for (int i = 0; i < 8; i++)
#pragma unroll
        for (int j = 0; j < 4; j++) { float v = outf[i][j]; s[j] += v; q[j] += v * v; }
    __syncthreads();
    int rg = tid >> 4;
#pragma unroll
    for (int j = 0; j < 4; j++) {
        s0[rg * 64 + col0 + j] = s[j];
        s1[rg * 64 + col0 + j] = q[j];
    }
    __syncthreads();
    if (tid < 64) {
        float S = 0.f, Q = 0.f;
#pragma unroll
        for (int g = 0; g < 16; g++) { S += s0[g * 64 + tid]; Q += s1[g * 64 + tid]; }
        atomicAdd(&gsum[colbase + tid], S);
        atomicAdd(&gssq[colbase + tid], Q);
    }
}

// 128x64 += 128x64 @ 64x64, stride-64 smem tiles (f32x2 SIMT path)
__device__ __forceinline__ void mm_tile64(const float* As, const float* Bs,
                                          int row0, int col0, u64 acc[8][2]) {
#pragma unroll 8
    for (int kk = 0; kk < 64; kk += 2) {
        ulonglong2 bv0 = *(const ulonglong2*)&Bs[kk * 64 + col0];
        ulonglong2 bv1 = *(const ulonglong2*)&Bs[(kk + 1) * 64 + col0];
#pragma unroll
        for (int i = 0; i < 8; i++) {
            float2 a = *(const float2*)&As[(row0 + i) * 64 + kk];
            u64 a0 = pk2(a.x), a1 = pk2(a.y);
            fma2(acc[i][0], a0, bv0.x);
            fma2(acc[i][1], a0, bv0.y);
            fma2(acc[i][0], a1, bv1.x);
            fma2(acc[i][1], a1, bv1.y);
        }
    }
}

// ---------------- GEMM1: g_h1 = x[N,256] @ W1[256,64]; cp.async pipelined; fused stats ----------------
__global__ __launch_bounds__(256) void k_gemm1(const float* __restrict__ x,
                                               const float* __restrict__ W1) {
    extern __shared__ float smem[];
    float* As = smem;                // 2 * 128*64
    float* Bs = smem + 2 * 128 * 64; // 2 * 64*64
    const int tid  = threadIdx.x;
    const int p0   = blockIdx.x * 128;
    const int nval = (NPTS - p0 < 128) ? (NPTS - p0) : 128;
    const int row0 = (tid >> 4) << 3;
    const int col0 = (tid & 15) << 2;
    u64 acc[8][2] = {};

    auto issue = [&](int kc, int buf) {
        float* Ad = As + buf * 8192;
        float* Bd = Bs + buf * 4096;
#pragma unroll
        for (int i = 0; i < 8; i++) {
            int j4 = tid + i * 256;
            int r = j4 >> 4, c = (j4 & 15) << 2;
            int re = (r < nval) ? r : 0;
            cpa16(sptr(&Ad[r * 64 + c]), x + (size_t)(p0 + re) * INC + kc * 64 + c);
        }
#pragma unroll
        for (int i = 0; i < 4; i++) {
            int j4 = tid + i * 256;
            int r = j4 >> 4, c = (j4 & 15) << 2;
            cpa16(sptr(&Bd[r * 64 + c]), W1 + (size_t)(kc * 64 + r) * MIDC + c);
        }
        cpa_commit();
    };

    issue(0, 0);
    for (int kc = 0; kc < 4; kc++) {
        int cur = kc & 1;
        if (kc + 1 < 4) { issue(kc + 1, cur ^ 1); cpa_wait<1>(); }
        else cpa_wait<0>();
        __syncthreads();
        mm_tile64(As + cur * 8192, Bs + cur * 4096, row0, col0, acc);
        __syncthreads();
    }

    float outf[8][4];
#pragma unroll
    for (int i = 0; i < 8; i++) {
        float2 p = up2(acc[i][0]), q = up2(acc[i][1]);
        bool v = (row0 + i) < nval;
        outf[i][0] = v ? p.x : 0.f; outf[i][1] = v ? p.y : 0.f;
        outf[i][2] = v ? q.x : 0.f; outf[i][3] = v ? q.y : 0.f;
        if (v)
            *(float4*)&g_h1[(size_t)(p0 + row0 + i) * MIDC + col0] =
                make_float4(p.x, p.y, q.x, q.y);
    }
    block_stats8(outf, As, Bs, tid, col0, g_sum1, g_ssq1, 0);
}

// ---------------- BN finalize ----------------
__global__ void k_finalize(const float* __restrict__ g, const float* __restrict__ b, int which) {
    int i = threadIdx.x;
    int C = (which == 2) ? OUTC : MIDC;
    if (i >= C) return;
    const float* sum = (which == 0) ? g_sum1 : (which == 1) ? g_sum2 : g_sum3;
    const float* ssq = (which == 0) ? g_ssq1 : (which == 1) ? g_ssq2 : g_ssq3;
    float* a = (which == 0) ? g_a1 : (which == 1) ? g_a2 : g_a3;
    float* c = (which == 0) ? g_c1 : (which == 1) ? g_c2 : g_c3;
    float m = sum[i] * (1.f / NPTS);
    float v = ssq[i] * (1.f / NPTS) - m * m;
    float ai = g[i] * rsqrtf(v + EPSV);
    a[i] = ai;
    c[i] = b[i] - m * ai;
}

// ---------------- norm1: g_r1 = relu(bn1(g_h1)) ----------------
__global__ __launch_bounds__(256) void k_norm1() {
    const size_t total4 = (size_t)NPTS * MIDC / 4;
    for (size_t i4 = (size_t)blockIdx.x * blockDim.x + threadIdx.x; i4 < total4;
         i4 += (size_t)gridDim.x * blockDim.x) {
        int c = (int)((i4 * 4) & (MIDC - 1));
        float4 v = *(const float4*)&g_h1[i4 * 4];
        v.x = fmaxf(fmaf(v.x, g_a1[c + 0], g_c1[c + 0]), 0.f);
        v.y = fmaxf(fmaf(v.y, g_a1[c + 1], g_c1[c + 1]), 0.f);
        v.z = fmaxf(fmaf(v.z, g_a1[c + 2], g_c1[c + 2]), 0.f);
        v.w = fmaxf(fmaf(v.w, g_a1[c + 3], g_c1[c + 3]), 0.f);
        *(float4*)&g_r1[i4 * 4] = v;
    }
}

// ---------------- gather GEMM via tf32 mma.sync; cp.async pipelined ----------------
// Block tile 128x64. 8 warps: warp w -> rows 32*(w&3).., cols 32*(w>>2)..
__global__ __launch_bounds__(256) void k_gather(const int* __restrict__ nbr,
                                                const float* __restrict__ W3) {
    extern __shared__ float smem[];
    float* As = smem;                            // 2 * 128*PADK
    float* Bs = smem + 2 * 128 * PADK;           // 2 * 64*PADK
    int*   sidx = (int*)(smem + 2 * 192 * PADK); // 128*KNB
    const int tid  = threadIdx.x;
    const int lane = tid & 31;
    const int w    = tid >> 5;
    const int p0   = blockIdx.x * 128;
    const int nval = (NPTS - p0 < 128) ? (NPTS - p0) : 128;
    const int rm = (w & 3) * 32;
    const int cn = (w >> 2) * 32;
    const int gid = lane >> 2;   // 0..7
    const int tig = lane & 3;    // 0..3

    for (int i = tid; i < nval * KNB; i += 256) sidx[i] = nbr[(size_t)p0 * KNB + i];
    __syncthreads();

    auto issue = [&](int k, int buf) {
        float* Bd = Bs + buf * 64 * PADK;
        const float* wb = W3 + (size_t)k * MIDC * MIDC;
#pragma unroll
        for (int i = 0; i < 4; i++) {
            int j4 = tid + i * 256;
            int r = j4 >> 4, c = (j4 & 15) << 2;
            cpa16(sptr(&Bd[r * PADK + c]), wb + r * 64 + c);
        }
        float* Ad = As + buf * 128 * PADK;
#pragma unroll
        for (int i = 0; i < 8; i++) {
            int j4 = tid + i * 256;
            int r = j4 >> 4, c = (j4 & 15) << 2;
            int ridx = (r < nval) ? sidx[r * KNB + k] : 0;
            cpa16(sptr(&Ad[r * PADK + c]), g_r1 + (size_t)ridx * MIDC + c);
        }
        cpa_commit();
    };

    float acc[2][4][4] = {};
    issue(0, 0);
    for (int k = 0; k < KNB; k++) {
        int cur = k & 1;
        if (k + 1 < KNB) { issue(k + 1, cur ^ 1); cpa_wait<1>(); }
        else cpa_wait<0>();
        __syncthreads();
        const float* A = As + cur * 128 * PADK;
        const float* B = Bs + cur * 64 * PADK;
#pragma unroll
        for (int kk = 0; kk < 8; kk++) {
            const int kc = kk * 8;
            u32 a[2][4], b[4][2];
#pragma unroll
            for (int mi = 0; mi < 2; mi++) {
                int row = rm + 16 * mi + gid;
                a[mi][0] = *(const u32*)&A[row * PADK + kc + tig];
                a[mi][1] = *(const u32*)&A[(row + 8) * PADK + kc + tig];
                a[mi][2] = *(const u32*)&A[row * PADK + kc + tig + 4];
                a[mi][3] = *(const u32*)&A[(row + 8) * PADK + kc + tig + 4];
            }
#pragma unroll
            for (int ni = 0; ni < 4; ni++) {
                int bc = cn + 8 * ni + gid;
                b[ni][0] = *(const u32*)&B[(kc + tig) * PADK + bc];
                b[ni][1] = *(const u32*)&B[(kc + tig + 4) * PADK + bc];
            }
#pragma unroll
            for (int mi = 0; mi < 2; mi++)
#pragma unroll
                for (int ni = 0; ni < 4; ni++)
                    mma_tf32(acc[mi][ni], a[mi][0], a[mi][1], a[mi][2], a[mi][3],
                             b[ni][0], b[ni][1]);
        }
        __syncthreads();
    }

    // store: c0,c1 at (row, col..col+1), c2,c3 at (row+8, col..col+1)
#pragma unroll
    for (int mi = 0; mi < 2; mi++) {
        int row = rm + 16 * mi + gid;
#pragma unroll
        for (int ni = 0; ni < 4; ni++) {
            int col = cn + 8 * ni + 2 * tig;
            if (row < nval)
                *(float2*)&g_h2[(size_t)(p0 + row) * MIDC + col] =
                    make_float2(acc[mi][ni][0], acc[mi][ni][1]);
            if (row + 8 < nval)
                *(float2*)&g_h2[(size_t)(p0 + row + 8) * MIDC + col] =
                    make_float2(acc[mi][ni][2], acc[mi][ni][3]);
        }
    }
}

// ---------------- column stats for g_h2 [N,64] ----------------
__global__ __launch_bounds__(256) void k_stats2() {
    int tid = threadIdx.x;
    int c = tid & 63, sub = tid >> 6;
    float s = 0.f, q = 0.f;
    for (int r = blockIdx.x * 4 + sub; r < NPTS; r += gridDim.x * 4) {
        float v = g_h2[(size_t)r * MIDC + c];
        s += v; q += v * v;
    }
    __shared__ float ss[256], qq[256];
    ss[tid] = s; qq[tid] = q;
    __syncthreads();
    if (tid < 64) {
        s = ss[tid] + ss[tid + 64] + ss[tid + 128] + ss[tid + 192];
        q = qq[tid] + qq[tid + 64] + qq[tid + 128] + qq[tid + 192];
        atomicAdd(&g_sum2[tid], s);
        atomicAdd(&g_ssq2[tid], q);
    }
}

// ---------------- GEMM2: g_h3 = relu(bn2(g_h2)) @ W2[64,256]; fused stats ----------------
__global__ __launch_bounds__(256) void k_gemm2(const float* __restrict__ W2) {
    extern __shared__ float smem[];
    float* As = smem;             // 128*64
    float* Bs = smem + 128 * 64;  // 64*64
    float* sa = smem + 192 * 64;
    float* sc = sa + MIDC;
    const int tid = threadIdx.x;
    const int p0  = blockIdx.x * 128;
    const int cb  = blockIdx.y * 64;
    const int nval = (NPTS - p0 < 128) ? (NPTS - p0) : 128;
    if (tid < MIDC) { sa[tid] = g_a2[tid]; sc[tid] = g_c2[tid]; }
    __syncthreads();
#pragma unroll
    for (int i = 0; i < 8; i++) {
        int j4 = tid + i * 256;
        int r = j4 >> 4, c = (j4 & 15) << 2;
        int re = (r < nval) ? r : 0;
        float4 v = *(const float4*)&g_h2[(size_t)(p0 + re) * MIDC + c];
        v.x = fmaxf(fmaf(v.x, sa[c + 0], sc[c + 0]), 0.f);
        v.y = fmaxf(fmaf(v.y, sa[c + 1], sc[c + 1]), 0.f);
        v.z = fmaxf(fmaf(v.z, sa[c + 2], sc[c + 2]), 0.f);
        v.w = fmaxf(fmaf(v.w, sa[c + 3], sc[c + 3]), 0.f);
        *(float4*)&As[r * 64 + c] = v;
    }
#pragma unroll
    for (int i = 0; i < 4; i++) {
        int j4 = tid + i * 256;
        int r = j4 >> 4, c = (j4 & 15) << 2;
        *(float4*)&Bs[r * 64 + c] = *(const float4*)(W2 + (size_t)r * OUTC + cb + c);
    }
    __syncthreads();
    const int row0 = (tid >> 4) << 3;
    const int col0 = (tid & 15) << 2;
    u64 acc[8][2] = {};
    mm_tile64(As, Bs, row0, col0, acc);

    float outf[8][4];
#pragma unroll
    for (int i = 0; i < 8; i++) {
        float2 p = up2(acc[i][0]), q = up2(acc[i][1]);
        bool v = (row0 + i) < nval;
        outf[i][0] = v ? p.x : 0.f; outf[i][1] = v ? p.y : 0.f;
        outf[i][2] = v ? q.x : 0.f; outf[i][3] = v ? q.y : 0.f;
        if (v)
            *(float4*)&g_h3[(size_t)(p0 + row0 + i) * OUTC + cb + col0] =
                make_float4(p.x, p.y, q.x, q.y);
    }
    block_stats8(outf, As, Bs, tid, col0, g_sum3, g_ssq3, cb);
}

// ---------------- epilogue: out = relu(bn3(h3) + x) ----------------
__global__ __launch_bounds__(256) void k_out(const float* __restrict__ x,
                                             float* __restrict__ out) {
    const size_t total4 = (size_t)NPTS * OUTC / 4;
    for (size_t i4 = (size_t)blockIdx.x * blockDim.x + threadIdx.x; i4 < total4;
         i4 += (size_t)gridDim.x * blockDim.x) {
        int c = (int)((i4 * 4) & (OUTC - 1));
        float4 h  = *(const float4*)&g_h3[i4 * 4];
        float4 xv = ((const float4*)x)[i4];
        float4 o;
        o.x = fmaxf(fmaf(h.x, g_a3[c + 0], g_c3[c + 0]) + xv.x, 0.f);
        o.y = fmaxf(fmaf(h.y, g_a3[c + 1], g_c3[c + 1]) + xv.y, 0.f);
        o.z = fmaxf(fmaf(h.z, g_a3[c + 2], g_c3[c + 2]) + xv.z, 0.f);
        o.w = fmaxf(fmaf(h.w, g_a3[c + 3], g_c3[c + 3]) + xv.w, 0.f);
        ((float4*)out)[i4] = o;
    }
}

// ---------------- launch ----------------
extern "C" void kernel_launch(void* const* d_in, const int* in_sizes, int n_in,
                              void* d_out, int out_size) {
    const float* x   = (const float*)d_in[0];
    const int*   nbr = (const int*)d_in[1];
    const float* W1  = (const float*)d_in[2];
    const float* W3  = (const float*)d_in[3];
    const float* W2  = (const float*)d_in[4];
    const float* g1  = (const float*)d_in[5];
    const float* b1  = (const float*)d_in[6];
    const float* g2  = (const float*)d_in[7];
    const float* b2  = (const float*)d_in[8];
    const float* g3  = (const float*)d_in[9];
    const float* b3  = (const float*)d_in[10];
    float* out = (float*)d_out;

    const int SM_G1  = (2 * 128 * 64 + 2 * 64 * 64) * 4;              // 96 KB
    const int SM_GAT = 2 * 192 * PADK * 4 + 128 * KNB * 4;            // ~115.5 KB
    const int SM_G2  = (128 * 64 + 64 * 64) * 4 + 2 * MIDC * 4;       // ~48.5 KB
    static bool attr_done = false;
    if (!attr_done) {
        cudaFuncSetAttribute(k_gemm1, cudaFuncAttributeMaxDynamicSharedMemorySize, SM_G1);
        cudaFuncSetAttribute(k_gather, cudaFuncAttributeMaxDynamicSharedMemorySize, SM_GAT);
        cudaFuncSetAttribute(k_gemm2, cudaFuncAttributeMaxDynamicSharedMemorySize, SM_G2);
        attr_done = true;
    }

    const int GB = (NPTS + 127) / 128;  // 938
    k_zero<<<1, 256>>>();
    k_gemm1<<<GB, 256, SM_G1>>>(x, W1);
    k_finalize<<<1, 256>>>(g1, b1, 0);
    k_norm1<<<2048, 256>>>();
    k_gather<<<GB, 256, SM_GAT>>>(nbr, W3);
    k_stats2<<<512, 256>>>();
    k_finalize<<<1, 256>>>(g2, b2, 1);
    dim3 grid2(GB, 4);
    k_gemm2<<<grid2, 256, SM_G2>>>(W2);
    k_finalize<<<1, 256>>>(g3, b3, 2);
    k_out<<<2048, 256>>>(x, out);
}